// round 8
// baseline (speedup 1.0000x reference)
#include <cuda_runtime.h>
#include <cuda_fp16.h>

#define NN 20000
#define EE 320000
#define TT 16
#define FIN 9
#define HID 128
#define HEADS 8
#define D1 1024          // HEADS*HID
#define PBLK 160
#define PCH 125          // 160*125 = 20000
#define FULL 0xffffffffu

// ---------------- static device scratch ----------------
__device__ int   g_is64;
__device__ int   g_cnt[NN];
__device__ int   g_rowptr[NN + 1];
__device__ int   g_cursor[NN];
__device__ int   g_col[EE];
__device__ float g_w1as[FIN * HEADS];
__device__ float g_w1ad[FIN * HEADS];
__device__ float g_als1[(size_t)TT * NN * HEADS];
__device__ float g_ald1[(size_t)TT * NN * HEADS];
__device__ float g_xagg[(size_t)TT * NN * 72];
__device__ __align__(16) __half g_W2h[D1 * HID];
__device__ __align__(16) __half g_h2[(size_t)TT * NN * HID];
__device__ float g_als2[(size_t)TT * NN];
__device__ float g_ald2[(size_t)TT * NN];
__device__ __align__(16) __half g_out2h[(size_t)TT * NN * HID];
__device__ float g_partial[(size_t)TT * PBLK * HID];
__device__ float g_emb[TT * HID];

// ---------------- CSR setup ----------------
__global__ void k_zc() {
    int i = blockIdx.x * blockDim.x + threadIdx.x;
    if (i < NN) g_cnt[i] = 0;
}

// per-thread dtype detection (int64 vs int32 edge_index) + degree count
__global__ void k_count(const void* __restrict__ ei) {
    int e = blockIdx.x * blockDim.x + threadIdx.x;
    if (e >= EE) return;
    const long long* p64 = (const long long*)ei;
    int ok = 1;
#pragma unroll
    for (int q = 0; q < 8; q++) {
        long long v = p64[q];
        if (v < 0 || v >= NN) ok = 0;
    }
    if (e == 0) g_is64 = ok;
    int d = ok ? (int)p64[(size_t)EE + e] : ((const int*)ei)[(size_t)EE + e];
    if (d >= 0 && d < NN) atomicAdd(&g_cnt[d], 1);
}

__global__ void k_scan() {
    __shared__ int part[1024];
    int tid = threadIdx.x;
    const int CH = (NN + 1023) / 1024;
    int base = tid * CH;
    int s = 0;
    for (int i = 0; i < CH; i++) {
        int idx = base + i;
        if (idx < NN) s += g_cnt[idx];
    }
    part[tid] = s;
    __syncthreads();
    for (int off = 1; off < 1024; off <<= 1) {
        int v = (tid >= off) ? part[tid - off] : 0;
        __syncthreads();
        part[tid] += v;
        __syncthreads();
    }
    int run = part[tid] - s;
    for (int i = 0; i < CH; i++) {
        int idx = base + i;
        if (idx < NN) {
            g_rowptr[idx] = run;
            g_cursor[idx] = run;
            run += g_cnt[idx];
        }
    }
    if (tid == 1023) g_rowptr[NN] = part[1023];
}

__global__ void k_fill(const void* __restrict__ ei) {
    int e = blockIdx.x * blockDim.x + threadIdx.x;
    if (e < EE) {
        int is64 = g_is64;
        int s = is64 ? (int)((const long long*)ei)[e] : ((const int*)ei)[e];
        int d = is64 ? (int)((const long long*)ei)[(size_t)EE + e]
                     : ((const int*)ei)[(size_t)EE + e];
        if (s >= 0 && s < NN && d >= 0 && d < NN) {
            int p = atomicAdd(&g_cursor[d], 1);
            g_col[p] = s;
        }
    }
}

// ---------------- prep: W2 -> fp16, W1a projections ----------------
__global__ void k_prep(const float* __restrict__ W2, const float* __restrict__ W1,
                       const float* __restrict__ as1, const float* __restrict__ ad1) {
    int i = blockIdx.x * blockDim.x + threadIdx.x;
    if (i < D1 * HID) g_W2h[i] = __float2half(W2[i]);
    if (blockIdx.x == 0 && threadIdx.x < FIN * HEADS) {
        int r = threadIdx.x / HEADS, h = threadIdx.x % HEADS;
        float s1 = 0.f, s2 = 0.f;
        for (int c = 0; c < HID; c++) {
            float wv = W1[r * D1 + h * HID + c];
            s1 += wv * as1[h * HID + c];
            s2 += wv * ad1[h * HID + c];
        }
        g_w1as[threadIdx.x] = s1;
        g_w1ad[threadIdx.x] = s2;
    }
}

// ---------------- GAT1 attention logits for all (t,n) ----------------
__global__ void __launch_bounds__(256) k_logits1(const float* __restrict__ x) {
    int id = blockIdx.x * blockDim.x + threadIdx.x;   // t*NN + n
    if (id >= TT * NN) return;
    float xv[FIN];
#pragma unroll
    for (int r = 0; r < FIN; r++) xv[r] = x[(size_t)id * FIN + r];
#pragma unroll
    for (int h = 0; h < HEADS; h++) {
        float s1 = 0.f, s2 = 0.f;
#pragma unroll
        for (int r = 0; r < FIN; r++) {
            s1 += xv[r] * g_w1as[r * HEADS + h];
            s2 += xv[r] * g_w1ad[r * HEADS + h];
        }
        g_als1[(size_t)id * HEADS + h] = s1;
        g_ald1[(size_t)id * HEADS + h] = s2;
    }
}

// ---------------- GAT1 aggregation in RAW feature space (warp-per-node) ----------------
__global__ void __launch_bounds__(256) k_agg1x(const float* __restrict__ x) {
    int w = threadIdx.x >> 5, lane = threadIdx.x & 31;
    int n = blockIdx.x * 8 + w;
    int t = blockIdx.y;
    if (n >= NN) return;
    const float* als = g_als1 + (size_t)t * NN * HEADS;
    const float* ald = g_ald1 + (size_t)t * NN * HEADS;
    const float* xt  = x + (size_t)t * NN * FIN;
    int start = g_rowptr[n];
    int deg = g_rowptr[n + 1] - start + 1;   // + self loop

    int h8 = lane & 7;
    float aldh = ald[n * HEADS + h8];

    float sum = 0.f;
    for (int i = lane >> 3; i < deg; i += 4) {
        int s = (i < deg - 1) ? g_col[start + i] : n;
        float l = als[s * HEADS + h8] + aldh;
        l = (l > 0.f) ? l : 0.2f * l;
        sum += __expf(l);
    }
    sum += __shfl_xor_sync(FULL, sum, 8);
    sum += __shfl_xor_sync(FULL, sum, 16);
    float inv = 1.f / (sum + 1e-16f);

    int h = lane >> 2, q = lane & 3;
    float invh = __shfl_sync(FULL, inv, h);
    float a0 = 0.f, a1 = 0.f, a2 = 0.f;
    const int* colp = &g_col[start];
    for (int i = 0; i < deg; i++) {
        int s = (i < deg - 1) ? colp[i] : n;
        float l = als[s * HEADS + h8] + aldh;
        l = (l > 0.f) ? l : 0.2f * l;
        float e = __expf(l);
        float alpha = __shfl_sync(FULL, e, h) * invh;
        const float* xs = &xt[(size_t)s * FIN];
        a0 += alpha * xs[q];
        a1 += alpha * xs[q + 4];
        if (q == 0) a2 += alpha * xs[8];
    }
    float* dst = &g_xagg[((size_t)t * NN + n) * 72 + h * FIN];
    dst[q] = a0;
    dst[q + 4] = a1;
    if (q == 0) dst[8] = a2;
}

// ---------------- fused GEMM: h2 = relu(xagg@W1 + b1) @ W2 ----------------
// smem: sW1h 4.5KB + sb1h 0.5KB + sXa 4.5KB + As 16KB + Bs 8KB = 33.5KB
__device__ __forceinline__ int aswz(int row, int col) {
    int chunk = col >> 3;
    int sw = chunk ^ (row & 7);
    return row * 64 + sw * 8 + (col & 7);
}
__device__ __forceinline__ int bswz(int row, int col) {
    int chunk = col >> 3;
    int sw = (chunk & 8) | ((chunk ^ row) & 7);
    return row * 128 + sw * 8 + (col & 7);
}

__global__ void __launch_bounds__(256) k_gemm2(const float* __restrict__ W1,
                                               const float* __restrict__ b1) {
    __shared__ float sW1h[FIN * HID];   // current head's 9x128 W1 slice
    __shared__ float sb1h[HID];
    __shared__ float sXa[128 * FIN];
    __shared__ __half As[128 * 64];
    __shared__ __half Bs[32 * 128];
    int tid = threadIdx.x;
    int lane = tid & 31, w = tid >> 5;
    int wm = w & 3, wn = w >> 2;
    int m0 = blockIdx.x * 128;
    int t = blockIdx.y;

    float acc[2][8][4];
#pragma unroll
    for (int mt = 0; mt < 2; mt++)
#pragma unroll
        for (int nt = 0; nt < 8; nt++)
#pragma unroll
            for (int q = 0; q < 4; q++) acc[mt][nt][q] = 0.f;

    int brow = tid >> 3;
    int bc0 = (tid & 7) * 2;
    int arow = tid >> 1;
    int kbase = (tid & 1) * 16;

    for (int h = 0; h < HEADS; h++) {
        // stage this head's W1 slice, bias slice, and xagg block
        for (int i = tid; i < FIN * HID; i += 256) {
            int r = i >> 7, c = i & 127;
            sW1h[i] = W1[r * D1 + h * HID + c];
        }
        if (tid < HID) sb1h[tid] = b1[h * HID + tid];
        for (int i = tid; i < 128 * FIN; i += 256) {
            int row = i / FIN, r = i - row * FIN;
            int gr = m0 + row;
            sXa[i] = (gr < NN) ? g_xagg[((size_t)t * NN + gr) * 72 + h * FIN + r] : 0.f;
        }
        __syncthreads();
        float xr[FIN];
#pragma unroll
        for (int r = 0; r < FIN; r++) xr[r] = sXa[arow * FIN + r];

        for (int kt = 0; kt < 4; kt++) {
            int k0 = h * HID + kt * 32;       // global K offset (for W2)
            int kl0 = kt * 32;                // local K offset within head
#pragma unroll
            for (int c = 0; c < 2; c++) {
                int ch = bc0 + c;
                *(uint4*)&Bs[bswz(brow, ch * 8)] =
                    *(const uint4*)&g_W2h[(size_t)(k0 + brow) * HID + ch * 8];
            }
            // A-tile generation: A[row][kk] = relu(b1 + xagg . W1)
#pragma unroll
            for (int kk = 0; kk < 16; kk += 2) {
                int k = kl0 + kbase + kk;     // 0..127 within head
                float v0 = sb1h[k], v1 = sb1h[k + 1];
#pragma unroll
                for (int r = 0; r < FIN; r++) {
                    v0 += xr[r] * sW1h[r * HID + k];
                    v1 += xr[r] * sW1h[r * HID + k + 1];
                }
                v0 = fmaxf(v0, 0.f);
                v1 = fmaxf(v1, 0.f);
                *(__half2*)&As[aswz(arow, kbase + kk)] = __floats2half2_rn(v0, v1);
            }
            __syncthreads();

#pragma unroll
            for (int kk = 0; kk < 32; kk += 16) {
                unsigned a[2][4];
#pragma unroll
                for (int mt = 0; mt < 2; mt++) {
                    int r = wm * 32 + mt * 16 + (lane & 15);
                    int cc = kk + (lane >> 4) * 8;
                    unsigned addr = (unsigned)__cvta_generic_to_shared(&As[aswz(r, cc)]);
                    asm volatile("ldmatrix.sync.aligned.m8n8.x4.shared.b16 {%0,%1,%2,%3}, [%4];"
                                 : "=r"(a[mt][0]), "=r"(a[mt][1]), "=r"(a[mt][2]), "=r"(a[mt][3])
                                 : "r"(addr));
                }
                unsigned b[8][2];
#pragma unroll
                for (int nt = 0; nt < 8; nt++) {
                    int r = kk + (lane & 15);
                    int cc = wn * 64 + nt * 8;
                    unsigned addr = (unsigned)__cvta_generic_to_shared(&Bs[bswz(r, cc)]);
                    asm volatile("ldmatrix.sync.aligned.m8n8.x2.trans.shared.b16 {%0,%1}, [%2];"
                                 : "=r"(b[nt][0]), "=r"(b[nt][1]) : "r"(addr));
                }
#pragma unroll
                for (int mt = 0; mt < 2; mt++)
#pragma unroll
                    for (int nt = 0; nt < 8; nt++) {
                        asm volatile(
                            "mma.sync.aligned.m16n8k16.row.col.f32.f16.f16.f32 "
                            "{%0,%1,%2,%3}, {%4,%5,%6,%7}, {%8,%9}, {%0,%1,%2,%3};"
                            : "+f"(acc[mt][nt][0]), "+f"(acc[mt][nt][1]),
                              "+f"(acc[mt][nt][2]), "+f"(acc[mt][nt][3])
                            : "r"(a[mt][0]), "r"(a[mt][1]), "r"(a[mt][2]), "r"(a[mt][3]),
                              "r"(b[nt][0]), "r"(b[nt][1]));
                    }
            }
            __syncthreads();
        }
    }

    __half* h2 = g_h2 + (size_t)t * NN * HID;
#pragma unroll
    for (int mt = 0; mt < 2; mt++) {
        int rbase = m0 + wm * 32 + mt * 16 + (lane >> 2);
#pragma unroll
        for (int nt = 0; nt < 8; nt++) {
            int col = wn * 64 + nt * 8 + (lane & 3) * 2;
            if (rbase < NN)
                *(__half2*)&h2[(size_t)rbase * HID + col] =
                    __floats2half2_rn(acc[mt][nt][0], acc[mt][nt][1]);
            if (rbase + 8 < NN)
                *(__half2*)&h2[(size_t)(rbase + 8) * HID + col] =
                    __floats2half2_rn(acc[mt][nt][2], acc[mt][nt][3]);
        }
    }
}

// ---------------- GAT2 attention logits (batched) ----------------
__global__ void __launch_bounds__(256) k_al2(const float* __restrict__ as2,
                                             const float* __restrict__ ad2) {
    int w = threadIdx.x >> 5, lane = threadIdx.x & 31;
    int n = blockIdx.x * 8 + w;
    int t = blockIdx.y;
    if (n >= NN) return;
    uint2 v = *(const uint2*)&g_h2[((size_t)t * NN + n) * HID + lane * 4];
    float2 f0 = __half22float2(*(__half2*)&v.x);
    float2 f1 = __half22float2(*(__half2*)&v.y);
    float4 a = *(const float4*)&as2[lane * 4];
    float4 d = *(const float4*)&ad2[lane * 4];
    float ps = f0.x * a.x + f0.y * a.y + f1.x * a.z + f1.y * a.w;
    float pd = f0.x * d.x + f0.y * d.y + f1.x * d.z + f1.y * d.w;
#pragma unroll
    for (int off = 16; off; off >>= 1) {
        ps += __shfl_xor_sync(FULL, ps, off);
        pd += __shfl_xor_sync(FULL, pd, off);
    }
    if (lane == 0) {
        g_als2[(size_t)t * NN + n] = ps;
        g_ald2[(size_t)t * NN + n] = pd;
    }
}

// ---------------- GAT2 softmax + aggregation (batched) ----------------
__global__ void __launch_bounds__(256) k_agg2(const float* __restrict__ b2) {
    int w = threadIdx.x >> 5, lane = threadIdx.x & 31;
    int n = blockIdx.x * 8 + w;
    int t = blockIdx.y;
    if (n >= NN) return;
    const __half* h2 = g_h2 + (size_t)t * NN * HID;
    const float* als = g_als2 + (size_t)t * NN;
    int start = g_rowptr[n];
    int deg = g_rowptr[n + 1] - start + 1;
    float aldn = g_ald2[(size_t)t * NN + n];

    float sum = 0.f;
    for (int i = lane; i < deg; i += 32) {
        int s = (i < deg - 1) ? g_col[start + i] : n;
        float l = als[s] + aldn;
        l = (l > 0.f) ? l : 0.2f * l;
        sum += __expf(l);
    }
#pragma unroll
    for (int off = 16; off; off >>= 1) sum += __shfl_xor_sync(FULL, sum, off);
    float inv = 1.f / (sum + 1e-16f);

    float a0 = 0.f, a1 = 0.f, a2 = 0.f, a3 = 0.f;
    const int* colp = &g_col[start];
    for (int i = 0; i < deg; i++) {
        int s = (i < deg - 1) ? colp[i] : n;
        float l = als[s] + aldn;
        l = (l > 0.f) ? l : 0.2f * l;
        float al = __expf(l) * inv;
        uint2 v = *(const uint2*)&h2[(size_t)s * HID + lane * 4];
        float2 f0 = __half22float2(*(__half2*)&v.x);
        float2 f1 = __half22float2(*(__half2*)&v.y);
        a0 += al * f0.x; a1 += al * f0.y;
        a2 += al * f1.x; a3 += al * f1.y;
    }
    float4 b = *(const float4*)&b2[lane * 4];
    __half2 p0 = __floats2half2_rn(fmaxf(a0 + b.x, 0.f), fmaxf(a1 + b.y, 0.f));
    __half2 p1 = __floats2half2_rn(fmaxf(a2 + b.z, 0.f), fmaxf(a3 + b.w, 0.f));
    uint2 o;
    o.x = *(unsigned*)&p0; o.y = *(unsigned*)&p1;
    *(uint2*)&g_out2h[((size_t)t * NN + n) * HID + lane * 4] = o;
}

// ---------------- deterministic mean pool (batched) ----------------
__global__ void __launch_bounds__(128) k_pool_a() {
    int c = threadIdx.x, b = blockIdx.x, t = blockIdx.y;
    int n0 = b * PCH, n1 = min(n0 + PCH, NN);
    float s = 0.f;
    for (int n = n0; n < n1; n++)
        s += __half2float(g_out2h[((size_t)t * NN + n) * HID + c]);
    g_partial[((size_t)t * PBLK + b) * HID + c] = s;
}

__global__ void __launch_bounds__(128) k_pool_b() {
    int c = threadIdx.x, t = blockIdx.x;
    float s = 0.f;
    for (int b = 0; b < PBLK; b++) s += g_partial[((size_t)t * PBLK + b) * HID + c];
    g_emb[t * HID + c] = s * (1.0f / NN);
}

// ---------------- GRU + output head ----------------
__global__ void __launch_bounds__(128) k_gru(
    const float* __restrict__ wih, const float* __restrict__ whh,
    const float* __restrict__ bih, const float* __restrict__ bhh,
    const float* __restrict__ wout, const float* __restrict__ bout,
    float* __restrict__ out) {
    int tid = threadIdx.x;
    __shared__ float h[HID], xt[HID];
    __shared__ float red[4];
    h[tid] = 0.f;
    __syncthreads();
    for (int t = 0; t < TT; t++) {
        xt[tid] = g_emb[t * HID + tid];
        __syncthreads();
        float gi[3], gh[3];
#pragma unroll
        for (int q = 0; q < 3; q++) {
            int r = q * HID + tid;
            float s1 = bih[r], s2 = bhh[r];
            const float* wi = &wih[(size_t)r * HID];
            const float* wh = &whh[(size_t)r * HID];
            for (int c = 0; c < HID; c++) {
                s1 += xt[c] * wi[c];
                s2 += h[c] * wh[c];
            }
            gi[q] = s1;
            gh[q] = s2;
        }
        float r  = 1.f / (1.f + __expf(-(gi[0] + gh[0])));
        float z  = 1.f / (1.f + __expf(-(gi[1] + gh[1])));
        float nn = tanhf(gi[2] + r * gh[2]);
        float hn = (1.f - z) * nn + z * h[tid];
        __syncthreads();
        h[tid] = hn;
        __syncthreads();
        float v = hn * wout[tid];
        int lane = tid & 31, w = tid >> 5;
        for (int o = 16; o; o >>= 1) v += __shfl_down_sync(FULL, v, o);
        if (lane == 0) red[w] = v;
        __syncthreads();
        if (tid == 0) out[t] = red[0] + red[1] + red[2] + red[3] + bout[0];
        __syncthreads();
    }
}

// ---------------- launch ----------------
extern "C" void kernel_launch(void* const* d_in, const int* in_sizes, int n_in,
                              void* d_out, int out_size) {
    const float* x    = (const float*)d_in[0];
    const void*  ei   = d_in[1];
    const float* W1   = (const float*)d_in[2];
    const float* as1  = (const float*)d_in[3];
    const float* ad1  = (const float*)d_in[4];
    const float* b1   = (const float*)d_in[5];
    const float* W2   = (const float*)d_in[6];
    const float* as2  = (const float*)d_in[7];
    const float* ad2  = (const float*)d_in[8];
    const float* b2   = (const float*)d_in[9];
    const float* wih  = (const float*)d_in[10];
    const float* whh  = (const float*)d_in[11];
    const float* bih  = (const float*)d_in[12];
    const float* bhh  = (const float*)d_in[13];
    const float* wout = (const float*)d_in[14];
    const float* bout = (const float*)d_in[15];
    float* out = (float*)d_out;

    k_zc<<<(NN + 255) / 256, 256>>>();
    k_count<<<(EE + 255) / 256, 256>>>(ei);
    k_prep<<<(D1 * HID + 255) / 256, 256>>>(W2, W1, as1, ad1);
    k_logits1<<<(TT * NN + 255) / 256, 256>>>(x);
    k_scan<<<1, 1024>>>();
    k_fill<<<(EE + 255) / 256, 256>>>(ei);
    k_agg1x<<<dim3((NN + 7) / 8, TT), 256>>>(x);
    k_gemm2<<<dim3((NN + 127) / 128, TT), 256>>>(W1, b1);
    k_al2<<<dim3((NN + 7) / 8, TT), 256>>>(as2, ad2);
    k_agg2<<<dim3((NN + 7) / 8, TT), 256>>>(b2);
    k_pool_a<<<dim3(PBLK, TT), 128>>>();
    k_pool_b<<<TT, 128>>>();
    k_gru<<<1, 128>>>(wih, whh, bih, bhh, wout, bout, out);
}

// round 9
// speedup vs baseline: 1.0019x; 1.0019x over previous
#include <cuda_runtime.h>
#include <cuda_fp16.h>

#define NN 20000
#define EE 320000
#define TT 16
#define FIN 9
#define HID 128
#define HEADS 8
#define D1 1024          // HEADS*HID
#define PBLK 160
#define PCH 125          // 160*125 = 20000
#define FULL 0xffffffffu

// ---------------- static device scratch ----------------
__device__ int   g_is64;
__device__ int   g_cnt[NN];
__device__ int   g_rowptr[NN + 1];
__device__ int   g_cursor[NN];
__device__ int   g_col[EE];
__device__ float g_w1as[FIN * HEADS];
__device__ float g_w1ad[FIN * HEADS];
__device__ float g_als1[(size_t)TT * NN * HEADS];
__device__ float g_ald1[(size_t)TT * NN * HEADS];
__device__ float g_xagg[(size_t)TT * NN * 72];
__device__ __align__(16) __half g_W2h[D1 * HID];
__device__ __align__(16) __half g_h2[(size_t)TT * NN * HID];
__device__ float g_als2[(size_t)TT * NN];
__device__ float g_ald2[(size_t)TT * NN];
__device__ __align__(16) __half g_out2h[(size_t)TT * NN * HID];
__device__ float g_partial[(size_t)TT * PBLK * HID];
__device__ float g_emb[TT * HID];

// ---------------- CSR setup ----------------
__global__ void k_zc() {
    int i = blockIdx.x * blockDim.x + threadIdx.x;
    if (i < NN) g_cnt[i] = 0;
}

// per-thread dtype detection (int64 vs int32 edge_index) + degree count
__global__ void k_count(const void* __restrict__ ei) {
    int e = blockIdx.x * blockDim.x + threadIdx.x;
    if (e >= EE) return;
    const long long* p64 = (const long long*)ei;
    int ok = 1;
#pragma unroll
    for (int q = 0; q < 8; q++) {
        long long v = p64[q];
        if (v < 0 || v >= NN) ok = 0;
    }
    if (e == 0) g_is64 = ok;
    int d = ok ? (int)p64[(size_t)EE + e] : ((const int*)ei)[(size_t)EE + e];
    if (d >= 0 && d < NN) atomicAdd(&g_cnt[d], 1);
}

__global__ void k_scan() {
    __shared__ int part[1024];
    int tid = threadIdx.x;
    const int CH = (NN + 1023) / 1024;
    int base = tid * CH;
    int s = 0;
    for (int i = 0; i < CH; i++) {
        int idx = base + i;
        if (idx < NN) s += g_cnt[idx];
    }
    part[tid] = s;
    __syncthreads();
    for (int off = 1; off < 1024; off <<= 1) {
        int v = (tid >= off) ? part[tid - off] : 0;
        __syncthreads();
        part[tid] += v;
        __syncthreads();
    }
    int run = part[tid] - s;
    for (int i = 0; i < CH; i++) {
        int idx = base + i;
        if (idx < NN) {
            g_rowptr[idx] = run;
            g_cursor[idx] = run;
            run += g_cnt[idx];
        }
    }
    if (tid == 1023) g_rowptr[NN] = part[1023];
}

__global__ void k_fill(const void* __restrict__ ei) {
    int e = blockIdx.x * blockDim.x + threadIdx.x;
    if (e < EE) {
        int is64 = g_is64;
        int s = is64 ? (int)((const long long*)ei)[e] : ((const int*)ei)[e];
        int d = is64 ? (int)((const long long*)ei)[(size_t)EE + e]
                     : ((const int*)ei)[(size_t)EE + e];
        if (s >= 0 && s < NN && d >= 0 && d < NN) {
            int p = atomicAdd(&g_cursor[d], 1);
            g_col[p] = s;
        }
    }
}

// ---------------- prep: W2 -> fp16, W1a projections ----------------
__global__ void k_prep(const float* __restrict__ W2, const float* __restrict__ W1,
                       const float* __restrict__ as1, const float* __restrict__ ad1) {
    int i = blockIdx.x * blockDim.x + threadIdx.x;
    if (i < D1 * HID) g_W2h[i] = __float2half(W2[i]);
    if (blockIdx.x == 0 && threadIdx.x < FIN * HEADS) {
        int r = threadIdx.x / HEADS, h = threadIdx.x % HEADS;
        float s1 = 0.f, s2 = 0.f;
        for (int c = 0; c < HID; c++) {
            float wv = W1[r * D1 + h * HID + c];
            s1 += wv * as1[h * HID + c];
            s2 += wv * ad1[h * HID + c];
        }
        g_w1as[threadIdx.x] = s1;
        g_w1ad[threadIdx.x] = s2;
    }
}

// ---------------- GAT1 attention logits for all (t,n) ----------------
__global__ void __launch_bounds__(256) k_logits1(const float* __restrict__ x) {
    int id = blockIdx.x * blockDim.x + threadIdx.x;   // t*NN + n
    if (id >= TT * NN) return;
    float xv[FIN];
#pragma unroll
    for (int r = 0; r < FIN; r++) xv[r] = x[(size_t)id * FIN + r];
#pragma unroll
    for (int h = 0; h < HEADS; h++) {
        float s1 = 0.f, s2 = 0.f;
#pragma unroll
        for (int r = 0; r < FIN; r++) {
            s1 += xv[r] * g_w1as[r * HEADS + h];
            s2 += xv[r] * g_w1ad[r * HEADS + h];
        }
        g_als1[(size_t)id * HEADS + h] = s1;
        g_ald1[(size_t)id * HEADS + h] = s2;
    }
}

// ---------------- GAT1 aggregation in RAW feature space (warp-per-node) ----------------
__global__ void __launch_bounds__(256) k_agg1x(const float* __restrict__ x) {
    int w = threadIdx.x >> 5, lane = threadIdx.x & 31;
    int n = blockIdx.x * 8 + w;
    int t = blockIdx.y;
    if (n >= NN) return;
    const float* als = g_als1 + (size_t)t * NN * HEADS;
    const float* ald = g_ald1 + (size_t)t * NN * HEADS;
    const float* xt  = x + (size_t)t * NN * FIN;
    int start = g_rowptr[n];
    int deg = g_rowptr[n + 1] - start + 1;   // + self loop

    int h8 = lane & 7;
    float aldh = ald[n * HEADS + h8];

    float sum = 0.f;
    for (int i = lane >> 3; i < deg; i += 4) {
        int s = (i < deg - 1) ? g_col[start + i] : n;
        float l = als[s * HEADS + h8] + aldh;
        l = (l > 0.f) ? l : 0.2f * l;
        sum += __expf(l);
    }
    sum += __shfl_xor_sync(FULL, sum, 8);
    sum += __shfl_xor_sync(FULL, sum, 16);
    float inv = 1.f / (sum + 1e-16f);

    int h = lane >> 2, q = lane & 3;
    float invh = __shfl_sync(FULL, inv, h);
    float a0 = 0.f, a1 = 0.f, a2 = 0.f;
    const int* colp = &g_col[start];
    for (int i = 0; i < deg; i++) {
        int s = (i < deg - 1) ? colp[i] : n;
        float l = als[s * HEADS + h8] + aldh;
        l = (l > 0.f) ? l : 0.2f * l;
        float e = __expf(l);
        float alpha = __shfl_sync(FULL, e, h) * invh;
        const float* xs = &xt[(size_t)s * FIN];
        a0 += alpha * xs[q];
        a1 += alpha * xs[q + 4];
        if (q == 0) a2 += alpha * xs[8];
    }
    float* dst = &g_xagg[((size_t)t * NN + n) * 72 + h * FIN];
    dst[q] = a0;
    dst[q + 4] = a1;
    if (q == 0) dst[8] = a2;
}

// ---------------- fused GEMM: h2 = relu(xagg@W1 + b1) @ W2 ----------------
// smem: sW1h 4.5KB + sb1h 0.5KB + sXa 4.5KB + As 16KB + Bs 8KB = 33.5KB
__device__ __forceinline__ int aswz(int row, int col) {
    int chunk = col >> 3;
    int sw = chunk ^ (row & 7);
    return row * 64 + sw * 8 + (col & 7);
}
__device__ __forceinline__ int bswz(int row, int col) {
    int chunk = col >> 3;
    int sw = (chunk & 8) | ((chunk ^ row) & 7);
    return row * 128 + sw * 8 + (col & 7);
}

__global__ void __launch_bounds__(256) k_gemm2(const float* __restrict__ W1,
                                               const float* __restrict__ b1) {
    __shared__ float sW1h[FIN * HID];   // current head's 9x128 W1 slice
    __shared__ float sb1h[HID];
    __shared__ float sXa[128 * FIN];
    __shared__ __half As[128 * 64];
    __shared__ __half Bs[32 * 128];
    int tid = threadIdx.x;
    int lane = tid & 31, w = tid >> 5;
    int wm = w & 3, wn = w >> 2;
    int m0 = blockIdx.x * 128;
    int t = blockIdx.y;

    float acc[2][8][4];
#pragma unroll
    for (int mt = 0; mt < 2; mt++)
#pragma unroll
        for (int nt = 0; nt < 8; nt++)
#pragma unroll
            for (int q = 0; q < 4; q++) acc[mt][nt][q] = 0.f;

    int brow = tid >> 3;
    int bc0 = (tid & 7) * 2;
    int arow = tid >> 1;
    int kbase = (tid & 1) * 16;

    for (int h = 0; h < HEADS; h++) {
        // stage this head's W1 slice, bias slice, and xagg block
        for (int i = tid; i < FIN * HID; i += 256) {
            int r = i >> 7, c = i & 127;
            sW1h[i] = W1[r * D1 + h * HID + c];
        }
        if (tid < HID) sb1h[tid] = b1[h * HID + tid];
        for (int i = tid; i < 128 * FIN; i += 256) {
            int row = i / FIN, r = i - row * FIN;
            int gr = m0 + row;
            sXa[i] = (gr < NN) ? g_xagg[((size_t)t * NN + gr) * 72 + h * FIN + r] : 0.f;
        }
        __syncthreads();
        float xr[FIN];
#pragma unroll
        for (int r = 0; r < FIN; r++) xr[r] = sXa[arow * FIN + r];

        for (int kt = 0; kt < 4; kt++) {
            int k0 = h * HID + kt * 32;       // global K offset (for W2)
            int kl0 = kt * 32;                // local K offset within head
#pragma unroll
            for (int c = 0; c < 2; c++) {
                int ch = bc0 + c;
                *(uint4*)&Bs[bswz(brow, ch * 8)] =
                    *(const uint4*)&g_W2h[(size_t)(k0 + brow) * HID + ch * 8];
            }
            // A-tile generation: A[row][kk] = relu(b1 + xagg . W1)
#pragma unroll
            for (int kk = 0; kk < 16; kk += 2) {
                int k = kl0 + kbase + kk;     // 0..127 within head
                float v0 = sb1h[k], v1 = sb1h[k + 1];
#pragma unroll
                for (int r = 0; r < FIN; r++) {
                    v0 += xr[r] * sW1h[r * HID + k];
                    v1 += xr[r] * sW1h[r * HID + k + 1];
                }
                v0 = fmaxf(v0, 0.f);
                v1 = fmaxf(v1, 0.f);
                *(__half2*)&As[aswz(arow, kbase + kk)] = __floats2half2_rn(v0, v1);
            }
            __syncthreads();

#pragma unroll
            for (int kk = 0; kk < 32; kk += 16) {
                unsigned a[2][4];
#pragma unroll
                for (int mt = 0; mt < 2; mt++) {
                    int r = wm * 32 + mt * 16 + (lane & 15);
                    int cc = kk + (lane >> 4) * 8;
                    unsigned addr = (unsigned)__cvta_generic_to_shared(&As[aswz(r, cc)]);
                    asm volatile("ldmatrix.sync.aligned.m8n8.x4.shared.b16 {%0,%1,%2,%3}, [%4];"
                                 : "=r"(a[mt][0]), "=r"(a[mt][1]), "=r"(a[mt][2]), "=r"(a[mt][3])
                                 : "r"(addr));
                }
                unsigned b[8][2];
#pragma unroll
                for (int nt = 0; nt < 8; nt++) {
                    int r = kk + (lane & 15);
                    int cc = wn * 64 + nt * 8;
                    unsigned addr = (unsigned)__cvta_generic_to_shared(&Bs[bswz(r, cc)]);
                    asm volatile("ldmatrix.sync.aligned.m8n8.x2.trans.shared.b16 {%0,%1}, [%2];"
                                 : "=r"(b[nt][0]), "=r"(b[nt][1]) : "r"(addr));
                }
#pragma unroll
                for (int mt = 0; mt < 2; mt++)
#pragma unroll
                    for (int nt = 0; nt < 8; nt++) {
                        asm volatile(
                            "mma.sync.aligned.m16n8k16.row.col.f32.f16.f16.f32 "
                            "{%0,%1,%2,%3}, {%4,%5,%6,%7}, {%8,%9}, {%0,%1,%2,%3};"
                            : "+f"(acc[mt][nt][0]), "+f"(acc[mt][nt][1]),
                              "+f"(acc[mt][nt][2]), "+f"(acc[mt][nt][3])
                            : "r"(a[mt][0]), "r"(a[mt][1]), "r"(a[mt][2]), "r"(a[mt][3]),
                              "r"(b[nt][0]), "r"(b[nt][1]));
                    }
            }
            __syncthreads();
        }
    }

    __half* h2 = g_h2 + (size_t)t * NN * HID;
#pragma unroll
    for (int mt = 0; mt < 2; mt++) {
        int rbase = m0 + wm * 32 + mt * 16 + (lane >> 2);
#pragma unroll
        for (int nt = 0; nt < 8; nt++) {
            int col = wn * 64 + nt * 8 + (lane & 3) * 2;
            if (rbase < NN)
                *(__half2*)&h2[(size_t)rbase * HID + col] =
                    __floats2half2_rn(acc[mt][nt][0], acc[mt][nt][1]);
            if (rbase + 8 < NN)
                *(__half2*)&h2[(size_t)(rbase + 8) * HID + col] =
                    __floats2half2_rn(acc[mt][nt][2], acc[mt][nt][3]);
        }
    }
}

// ---------------- GAT2 attention logits (batched) ----------------
__global__ void __launch_bounds__(256) k_al2(const float* __restrict__ as2,
                                             const float* __restrict__ ad2) {
    int w = threadIdx.x >> 5, lane = threadIdx.x & 31;
    int n = blockIdx.x * 8 + w;
    int t = blockIdx.y;
    if (n >= NN) return;
    uint2 v = *(const uint2*)&g_h2[((size_t)t * NN + n) * HID + lane * 4];
    float2 f0 = __half22float2(*(__half2*)&v.x);
    float2 f1 = __half22float2(*(__half2*)&v.y);
    float4 a = *(const float4*)&as2[lane * 4];
    float4 d = *(const float4*)&ad2[lane * 4];
    float ps = f0.x * a.x + f0.y * a.y + f1.x * a.z + f1.y * a.w;
    float pd = f0.x * d.x + f0.y * d.y + f1.x * d.z + f1.y * d.w;
#pragma unroll
    for (int off = 16; off; off >>= 1) {
        ps += __shfl_xor_sync(FULL, ps, off);
        pd += __shfl_xor_sync(FULL, pd, off);
    }
    if (lane == 0) {
        g_als2[(size_t)t * NN + n] = ps;
        g_ald2[(size_t)t * NN + n] = pd;
    }
}

// ---------------- GAT2 softmax + aggregation (batched) ----------------
__global__ void __launch_bounds__(256) k_agg2(const float* __restrict__ b2) {
    int w = threadIdx.x >> 5, lane = threadIdx.x & 31;
    int n = blockIdx.x * 8 + w;
    int t = blockIdx.y;
    if (n >= NN) return;
    const __half* h2 = g_h2 + (size_t)t * NN * HID;
    const float* als = g_als2 + (size_t)t * NN;
    int start = g_rowptr[n];
    int deg = g_rowptr[n + 1] - start + 1;
    float aldn = g_ald2[(size_t)t * NN + n];

    float sum = 0.f;
    for (int i = lane; i < deg; i += 32) {
        int s = (i < deg - 1) ? g_col[start + i] : n;
        float l = als[s] + aldn;
        l = (l > 0.f) ? l : 0.2f * l;
        sum += __expf(l);
    }
#pragma unroll
    for (int off = 16; off; off >>= 1) sum += __shfl_xor_sync(FULL, sum, off);
    float inv = 1.f / (sum + 1e-16f);

    float a0 = 0.f, a1 = 0.f, a2 = 0.f, a3 = 0.f;
    const int* colp = &g_col[start];
    for (int i = 0; i < deg; i++) {
        int s = (i < deg - 1) ? colp[i] : n;
        float l = als[s] + aldn;
        l = (l > 0.f) ? l : 0.2f * l;
        float al = __expf(l) * inv;
        uint2 v = *(const uint2*)&h2[(size_t)s * HID + lane * 4];
        float2 f0 = __half22float2(*(__half2*)&v.x);
        float2 f1 = __half22float2(*(__half2*)&v.y);
        a0 += al * f0.x; a1 += al * f0.y;
        a2 += al * f1.x; a3 += al * f1.y;
    }
    float4 b = *(const float4*)&b2[lane * 4];
    __half2 p0 = __floats2half2_rn(fmaxf(a0 + b.x, 0.f), fmaxf(a1 + b.y, 0.f));
    __half2 p1 = __floats2half2_rn(fmaxf(a2 + b.z, 0.f), fmaxf(a3 + b.w, 0.f));
    uint2 o;
    o.x = *(unsigned*)&p0; o.y = *(unsigned*)&p1;
    *(uint2*)&g_out2h[((size_t)t * NN + n) * HID + lane * 4] = o;
}

// ---------------- deterministic mean pool (batched) ----------------
__global__ void __launch_bounds__(128) k_pool_a() {
    int c = threadIdx.x, b = blockIdx.x, t = blockIdx.y;
    int n0 = b * PCH, n1 = min(n0 + PCH, NN);
    float s = 0.f;
    for (int n = n0; n < n1; n++)
        s += __half2float(g_out2h[((size_t)t * NN + n) * HID + c]);
    g_partial[((size_t)t * PBLK + b) * HID + c] = s;
}

__global__ void __launch_bounds__(128) k_pool_b() {
    int c = threadIdx.x, t = blockIdx.x;
    float s = 0.f;
    for (int b = 0; b < PBLK; b++) s += g_partial[((size_t)t * PBLK + b) * HID + c];
    g_emb[t * HID + c] = s * (1.0f / NN);
}

// ---------------- GRU + output head ----------------
__global__ void __launch_bounds__(128) k_gru(
    const float* __restrict__ wih, const float* __restrict__ whh,
    const float* __restrict__ bih, const float* __restrict__ bhh,
    const float* __restrict__ wout, const float* __restrict__ bout,
    float* __restrict__ out) {
    int tid = threadIdx.x;
    __shared__ float h[HID], xt[HID];
    __shared__ float red[4];
    h[tid] = 0.f;
    __syncthreads();
    for (int t = 0; t < TT; t++) {
        xt[tid] = g_emb[t * HID + tid];
        __syncthreads();
        float gi[3], gh[3];
#pragma unroll
        for (int q = 0; q < 3; q++) {
            int r = q * HID + tid;
            float s1 = bih[r], s2 = bhh[r];
            const float* wi = &wih[(size_t)r * HID];
            const float* wh = &whh[(size_t)r * HID];
            for (int c = 0; c < HID; c++) {
                s1 += xt[c] * wi[c];
                s2 += h[c] * wh[c];
            }
            gi[q] = s1;
            gh[q] = s2;
        }
        float r  = 1.f / (1.f + __expf(-(gi[0] + gh[0])));
        float z  = 1.f / (1.f + __expf(-(gi[1] + gh[1])));
        float nn = tanhf(gi[2] + r * gh[2]);
        float hn = (1.f - z) * nn + z * h[tid];
        __syncthreads();
        h[tid] = hn;
        __syncthreads();
        float v = hn * wout[tid];
        int lane = tid & 31, w = tid >> 5;
        for (int o = 16; o; o >>= 1) v += __shfl_down_sync(FULL, v, o);
        if (lane == 0) red[w] = v;
        __syncthreads();
        if (tid == 0) out[t] = red[0] + red[1] + red[2] + red[3] + bout[0];
        __syncthreads();
    }
}

// ---------------- launch ----------------
extern "C" void kernel_launch(void* const* d_in, const int* in_sizes, int n_in,
                              void* d_out, int out_size) {
    const float* x    = (const float*)d_in[0];
    const void*  ei   = d_in[1];
    const float* W1   = (const float*)d_in[2];
    const float* as1  = (const float*)d_in[3];
    const float* ad1  = (const float*)d_in[4];
    const float* b1   = (const float*)d_in[5];
    const float* W2   = (const float*)d_in[6];
    const float* as2  = (const float*)d_in[7];
    const float* ad2  = (const float*)d_in[8];
    const float* b2   = (const float*)d_in[9];
    const float* wih  = (const float*)d_in[10];
    const float* whh  = (const float*)d_in[11];
    const float* bih  = (const float*)d_in[12];
    const float* bhh  = (const float*)d_in[13];
    const float* wout = (const float*)d_in[14];
    const float* bout = (const float*)d_in[15];
    float* out = (float*)d_out;

    k_zc<<<(NN + 255) / 256, 256>>>();
    k_count<<<(EE + 255) / 256, 256>>>(ei);
    k_prep<<<(D1 * HID + 255) / 256, 256>>>(W2, W1, as1, ad1);
    k_logits1<<<(TT * NN + 255) / 256, 256>>>(x);
    k_scan<<<1, 1024>>>();
    k_fill<<<(EE + 255) / 256, 256>>>(ei);
    k_agg1x<<<dim3((NN + 7) / 8, TT), 256>>>(x);
    k_gemm2<<<dim3((NN + 127) / 128, TT), 256>>>(W1, b1);
    k_al2<<<dim3((NN + 7) / 8, TT), 256>>>(as2, ad2);
    k_agg2<<<dim3((NN + 7) / 8, TT), 256>>>(b2);
    k_pool_a<<<dim3(PBLK, TT), 128>>>();
    k_pool_b<<<TT, 128>>>();
    k_gru<<<1, 128>>>(wih, whh, bih, bhh, wout, bout, out);
}

// round 10
// speedup vs baseline: 1.1170x; 1.1149x over previous
#include <cuda_runtime.h>
#include <cuda_fp16.h>

#define NN 20000
#define EE 320000
#define TT 16
#define FIN 9
#define HID 128
#define HEADS 8
#define D1 1024          // HEADS*HID
#define MM (TT * NN)     // 320000 flat rows
#define PBLK 160
#define PCH 125
#define FULL 0xffffffffu

// ---------------- static device scratch ----------------
__device__ int   g_is64;
__device__ int   g_cnt[NN];
__device__ int   g_rowptr[NN + 1];
__device__ int   g_cursor[NN];
__device__ int   g_col[EE];
__device__ float g_w1as[FIN * HEADS];
__device__ float g_w1ad[FIN * HEADS];
__device__ float g_als1[(size_t)TT * NN * HEADS];
__device__ float g_ald1[(size_t)TT * NN * HEADS];
__device__ float g_xagg[(size_t)TT * NN * 72];
__device__ __align__(16) __half g_out1[(size_t)MM * D1];   // 655 MB fp16
__device__ __align__(16) __half g_W2h[D1 * HID];
__device__ __align__(16) __half g_h2[(size_t)MM * HID];
__device__ float g_als2[(size_t)TT * NN];
__device__ float g_ald2[(size_t)TT * NN];
__device__ __align__(16) __half g_out2h[(size_t)TT * NN * HID];
__device__ float g_partial[(size_t)TT * PBLK * HID];
__device__ float g_emb[TT * HID];

// ---------------- CSR setup ----------------
__global__ void k_zc() {
    int i = blockIdx.x * blockDim.x + threadIdx.x;
    if (i < NN) g_cnt[i] = 0;
}

__global__ void k_count(const void* __restrict__ ei) {
    int e = blockIdx.x * blockDim.x + threadIdx.x;
    if (e >= EE) return;
    const long long* p64 = (const long long*)ei;
    int ok = 1;
#pragma unroll
    for (int q = 0; q < 8; q++) {
        long long v = p64[q];
        if (v < 0 || v >= NN) ok = 0;
    }
    if (e == 0) g_is64 = ok;
    int d = ok ? (int)p64[(size_t)EE + e] : ((const int*)ei)[(size_t)EE + e];
    if (d >= 0 && d < NN) atomicAdd(&g_cnt[d], 1);
}

__global__ void k_scan() {
    __shared__ int part[1024];
    int tid = threadIdx.x;
    const int CH = (NN + 1023) / 1024;
    int base = tid * CH;
    int s = 0;
    for (int i = 0; i < CH; i++) {
        int idx = base + i;
        if (idx < NN) s += g_cnt[idx];
    }
    part[tid] = s;
    __syncthreads();
    for (int off = 1; off < 1024; off <<= 1) {
        int v = (tid >= off) ? part[tid - off] : 0;
        __syncthreads();
        part[tid] += v;
        __syncthreads();
    }
    int run = part[tid] - s;
    for (int i = 0; i < CH; i++) {
        int idx = base + i;
        if (idx < NN) {
            g_rowptr[idx] = run;
            g_cursor[idx] = run;
            run += g_cnt[idx];
        }
    }
    if (tid == 1023) g_rowptr[NN] = part[1023];
}

__global__ void k_fill(const void* __restrict__ ei) {
    int e = blockIdx.x * blockDim.x + threadIdx.x;
    if (e < EE) {
        int is64 = g_is64;
        int s = is64 ? (int)((const long long*)ei)[e] : ((const int*)ei)[e];
        int d = is64 ? (int)((const long long*)ei)[(size_t)EE + e]
                     : ((const int*)ei)[(size_t)EE + e];
        if (s >= 0 && s < NN && d >= 0 && d < NN) {
            int p = atomicAdd(&g_cursor[d], 1);
            g_col[p] = s;
        }
    }
}

// ---------------- prep: W2 -> fp16, W1a projections ----------------
__global__ void k_prep(const float* __restrict__ W2, const float* __restrict__ W1,
                       const float* __restrict__ as1, const float* __restrict__ ad1) {
    int i = blockIdx.x * blockDim.x + threadIdx.x;
    if (i < D1 * HID) g_W2h[i] = __float2half(W2[i]);
    if (blockIdx.x == 0 && threadIdx.x < FIN * HEADS) {
        int r = threadIdx.x / HEADS, h = threadIdx.x % HEADS;
        float s1 = 0.f, s2 = 0.f;
        for (int c = 0; c < HID; c++) {
            float wv = W1[r * D1 + h * HID + c];
            s1 += wv * as1[h * HID + c];
            s2 += wv * ad1[h * HID + c];
        }
        g_w1as[threadIdx.x] = s1;
        g_w1ad[threadIdx.x] = s2;
    }
}

// ---------------- GAT1 attention logits for all (t,n) ----------------
__global__ void __launch_bounds__(256) k_logits1(const float* __restrict__ x) {
    int id = blockIdx.x * blockDim.x + threadIdx.x;
    if (id >= TT * NN) return;
    float xv[FIN];
#pragma unroll
    for (int r = 0; r < FIN; r++) xv[r] = x[(size_t)id * FIN + r];
#pragma unroll
    for (int h = 0; h < HEADS; h++) {
        float s1 = 0.f, s2 = 0.f;
#pragma unroll
        for (int r = 0; r < FIN; r++) {
            s1 += xv[r] * g_w1as[r * HEADS + h];
            s2 += xv[r] * g_w1ad[r * HEADS + h];
        }
        g_als1[(size_t)id * HEADS + h] = s1;
        g_ald1[(size_t)id * HEADS + h] = s2;
    }
}

// ---------------- GAT1 aggregation in RAW feature space (warp-per-node) ----------------
__global__ void __launch_bounds__(256) k_agg1x(const float* __restrict__ x) {
    int w = threadIdx.x >> 5, lane = threadIdx.x & 31;
    int n = blockIdx.x * 8 + w;
    int t = blockIdx.y;
    if (n >= NN) return;
    const float* als = g_als1 + (size_t)t * NN * HEADS;
    const float* ald = g_ald1 + (size_t)t * NN * HEADS;
    const float* xt  = x + (size_t)t * NN * FIN;
    int start = g_rowptr[n];
    int deg = g_rowptr[n + 1] - start + 1;

    int h8 = lane & 7;
    float aldh = ald[n * HEADS + h8];

    float sum = 0.f;
    for (int i = lane >> 3; i < deg; i += 4) {
        int s = (i < deg - 1) ? g_col[start + i] : n;
        float l = als[s * HEADS + h8] + aldh;
        l = (l > 0.f) ? l : 0.2f * l;
        sum += __expf(l);
    }
    sum += __shfl_xor_sync(FULL, sum, 8);
    sum += __shfl_xor_sync(FULL, sum, 16);
    float inv = 1.f / (sum + 1e-16f);

    int h = lane >> 2, q = lane & 3;
    float invh = __shfl_sync(FULL, inv, h);
    float a0 = 0.f, a1 = 0.f, a2 = 0.f;
    const int* colp = &g_col[start];
    for (int i = 0; i < deg; i++) {
        int s = (i < deg - 1) ? colp[i] : n;
        float l = als[s * HEADS + h8] + aldh;
        l = (l > 0.f) ? l : 0.2f * l;
        float e = __expf(l);
        float alpha = __shfl_sync(FULL, e, h) * invh;
        const float* xs = &xt[(size_t)s * FIN];
        a0 += alpha * xs[q];
        a1 += alpha * xs[q + 4];
        if (q == 0) a2 += alpha * xs[8];
    }
    float* dst = &g_xagg[((size_t)t * NN + n) * 72 + h * FIN];
    dst[q] = a0;
    dst[q + 4] = a1;
    if (q == 0) dst[8] = a2;
}

// ---------------- expand: out1 = relu(xagg @ W1 + b1)  (fp16, W1 in registers) ----------------
// block = 256 threads, 32 rows; thread owns 4 fixed columns (gcol = tid*4), head = tid>>5.
__global__ void __launch_bounds__(256) k_expand(const float* __restrict__ W1,
                                                const float* __restrict__ b1) {
    __shared__ float sxa[32 * 72];
    int tid = threadIdx.x;
    int gcol = tid * 4;
    int head = tid >> 5;
    int row0 = blockIdx.x * 32;

    float w[FIN][4];
#pragma unroll
    for (int r = 0; r < FIN; r++) {
        float4 wv = *(const float4*)&W1[r * D1 + gcol];
        w[r][0] = wv.x; w[r][1] = wv.y; w[r][2] = wv.z; w[r][3] = wv.w;
    }
    float4 bias = *(const float4*)&b1[gcol];

    for (int i = tid; i < 32 * 72; i += 256)
        sxa[i] = g_xagg[(size_t)row0 * 72 + i];
    __syncthreads();

    for (int rr = 0; rr < 32; rr++) {
        const float* xa = &sxa[rr * 72 + head * FIN];
        float v0 = bias.x, v1 = bias.y, v2 = bias.z, v3 = bias.w;
#pragma unroll
        for (int r = 0; r < FIN; r++) {
            float xr = xa[r];
            v0 += xr * w[r][0];
            v1 += xr * w[r][1];
            v2 += xr * w[r][2];
            v3 += xr * w[r][3];
        }
        __half2 p0 = __floats2half2_rn(fmaxf(v0, 0.f), fmaxf(v1, 0.f));
        __half2 p1 = __floats2half2_rn(fmaxf(v2, 0.f), fmaxf(v3, 0.f));
        uint2 o;
        o.x = *(unsigned*)&p0; o.y = *(unsigned*)&p1;
        *(uint2*)&g_out1[(size_t)(row0 + rr) * D1 + gcol] = o;
    }
}

// ---------------- pipelined TC GEMM: h2[MM,128] = out1[MM,1024] @ W2h ----------------
// BM=128, BK=32, BN=128; double-buffered cp.async; 1 syncthreads per K-chunk.
__device__ __forceinline__ int aswz32(int row, int col) {   // 32-half rows
    int chunk = (col >> 3) & 3;
    int sw = chunk ^ ((row >> 1) & 3);
    return row * 32 + sw * 8 + (col & 7);
}
__device__ __forceinline__ int bswz(int row, int col) {     // 128-half rows
    int chunk = col >> 3;
    int sw = (chunk & 8) | ((chunk ^ row) & 7);
    return row * 128 + sw * 8 + (col & 7);
}

__global__ void __launch_bounds__(256) k_gemm() {
    __shared__ __half As[2][128 * 32];
    __shared__ __half Bs[2][32 * 128];
    int tid = threadIdx.x;
    int lane = tid & 31, w = tid >> 5;
    int wm = w & 3, wn = w >> 2;
    size_t m0 = (size_t)blockIdx.x * 128;

    float acc[2][8][4];
#pragma unroll
    for (int mt = 0; mt < 2; mt++)
#pragma unroll
        for (int nt = 0; nt < 8; nt++)
#pragma unroll
            for (int q = 0; q < 4; q++) acc[mt][nt][q] = 0.f;

    int arow = tid >> 1;
    int ac0 = (tid & 1) * 2;
    int brow = tid >> 3;
    int bc0 = (tid & 7) * 2;

    const __half* aSrc0 = &g_out1[(m0 + arow) * D1];

#define ISSUE_STAGE(kt, buf)                                                          \
    do {                                                                              \
        _Pragma("unroll")                                                             \
        for (int c = 0; c < 2; c++) {                                                 \
            int ch = ac0 + c;                                                         \
            unsigned d_ = (unsigned)__cvta_generic_to_shared(                         \
                &As[buf][aswz32(arow, ch * 8)]);                                      \
            const __half* s_ = aSrc0 + (kt) * 32 + ch * 8;                            \
            asm volatile("cp.async.ca.shared.global [%0], [%1], 16;" ::               \
                         "r"(d_), "l"(s_));                                           \
        }                                                                             \
        _Pragma("unroll")                                                             \
        for (int c = 0; c < 2; c++) {                                                 \
            int ch = bc0 + c;                                                         \
            unsigned d_ = (unsigned)__cvta_generic_to_shared(                         \
                &Bs[buf][bswz(brow, ch * 8)]);                                        \
            const __half* s_ = &g_W2h[(size_t)((kt) * 32 + brow) * HID + ch * 8];     \
            asm volatile("cp.async.ca.shared.global [%0], [%1], 16;" ::               \
                         "r"(d_), "l"(s_));                                           \
        }                                                                             \
        asm volatile("cp.async.commit_group;");                                       \
    } while (0)

    ISSUE_STAGE(0, 0);

    for (int kt = 0; kt < 32; kt++) {
        int buf = kt & 1;
        asm volatile("cp.async.wait_group 0;");
        __syncthreads();
        if (kt + 1 < 32) ISSUE_STAGE(kt + 1, buf ^ 1);

#pragma unroll
        for (int kk = 0; kk < 32; kk += 16) {
            unsigned a[2][4];
#pragma unroll
            for (int mt = 0; mt < 2; mt++) {
                int r = wm * 32 + mt * 16 + (lane & 15);
                int cc = kk + (lane >> 4) * 8;
                unsigned addr = (unsigned)__cvta_generic_to_shared(&As[buf][aswz32(r, cc)]);
                asm volatile("ldmatrix.sync.aligned.m8n8.x4.shared.b16 {%0,%1,%2,%3}, [%4];"
                             : "=r"(a[mt][0]), "=r"(a[mt][1]), "=r"(a[mt][2]), "=r"(a[mt][3])
                             : "r"(addr));
            }
            unsigned b[8][2];
#pragma unroll
            for (int nt = 0; nt < 8; nt++) {
                int r = kk + (lane & 15);
                int cc = wn * 64 + nt * 8;
                unsigned addr = (unsigned)__cvta_generic_to_shared(&Bs[buf][bswz(r, cc)]);
                asm volatile("ldmatrix.sync.aligned.m8n8.x2.trans.shared.b16 {%0,%1}, [%2];"
                             : "=r"(b[nt][0]), "=r"(b[nt][1]) : "r"(addr));
            }
#pragma unroll
            for (int mt = 0; mt < 2; mt++)
#pragma unroll
                for (int nt = 0; nt < 8; nt++) {
                    asm volatile(
                        "mma.sync.aligned.m16n8k16.row.col.f32.f16.f16.f32 "
                        "{%0,%1,%2,%3}, {%4,%5,%6,%7}, {%8,%9}, {%0,%1,%2,%3};"
                        : "+f"(acc[mt][nt][0]), "+f"(acc[mt][nt][1]),
                          "+f"(acc[mt][nt][2]), "+f"(acc[mt][nt][3])
                        : "r"(a[mt][0]), "r"(a[mt][1]), "r"(a[mt][2]), "r"(a[mt][3]),
                          "r"(b[nt][0]), "r"(b[nt][1]));
                }
        }
        __syncthreads();
    }
#undef ISSUE_STAGE

#pragma unroll
    for (int mt = 0; mt < 2; mt++) {
        size_t rbase = m0 + wm * 32 + mt * 16 + (lane >> 2);
#pragma unroll
        for (int nt = 0; nt < 8; nt++) {
            int col = wn * 64 + nt * 8 + (lane & 3) * 2;
            *(__half2*)&g_h2[rbase * HID + col] =
                __floats2half2_rn(acc[mt][nt][0], acc[mt][nt][1]);
            *(__half2*)&g_h2[(rbase + 8) * HID + col] =
                __floats2half2_rn(acc[mt][nt][2], acc[mt][nt][3]);
        }
    }
}

// ---------------- GAT2 attention logits (batched) ----------------
__global__ void __launch_bounds__(256) k_al2(const float* __restrict__ as2,
                                             const float* __restrict__ ad2) {
    int w = threadIdx.x >> 5, lane = threadIdx.x & 31;
    int n = blockIdx.x * 8 + w;
    int t = blockIdx.y;
    if (n >= NN) return;
    uint2 v = *(const uint2*)&g_h2[((size_t)t * NN + n) * HID + lane * 4];
    float2 f0 = __half22float2(*(__half2*)&v.x);
    float2 f1 = __half22float2(*(__half2*)&v.y);
    float4 a = *(const float4*)&as2[lane * 4];
    float4 d = *(const float4*)&ad2[lane * 4];
    float ps = f0.x * a.x + f0.y * a.y + f1.x * a.z + f1.y * a.w;
    float pd = f0.x * d.x + f0.y * d.y + f1.x * d.z + f1.y * d.w;
#pragma unroll
    for (int off = 16; off; off >>= 1) {
        ps += __shfl_xor_sync(FULL, ps, off);
        pd += __shfl_xor_sync(FULL, pd, off);
    }
    if (lane == 0) {
        g_als2[(size_t)t * NN + n] = ps;
        g_ald2[(size_t)t * NN + n] = pd;
    }
}

// ---------------- GAT2 softmax + aggregation (batched) ----------------
__global__ void __launch_bounds__(256) k_agg2(const float* __restrict__ b2) {
    int w = threadIdx.x >> 5, lane = threadIdx.x & 31;
    int n = blockIdx.x * 8 + w;
    int t = blockIdx.y;
    if (n >= NN) return;
    const __half* h2 = g_h2 + (size_t)t * NN * HID;
    const float* als = g_als2 + (size_t)t * NN;
    int start = g_rowptr[n];
    int deg = g_rowptr[n + 1] - start + 1;
    float aldn = g_ald2[(size_t)t * NN + n];

    float sum = 0.f;
    for (int i = lane; i < deg; i += 32) {
        int s = (i < deg - 1) ? g_col[start + i] : n;
        float l = als[s] + aldn;
        l = (l > 0.f) ? l : 0.2f * l;
        sum += __expf(l);
    }
#pragma unroll
    for (int off = 16; off; off >>= 1) sum += __shfl_xor_sync(FULL, sum, off);
    float inv = 1.f / (sum + 1e-16f);

    float a0 = 0.f, a1 = 0.f, a2 = 0.f, a3 = 0.f;
    const int* colp = &g_col[start];
    for (int i = 0; i < deg; i++) {
        int s = (i < deg - 1) ? colp[i] : n;
        float l = als[s] + aldn;
        l = (l > 0.f) ? l : 0.2f * l;
        float al = __expf(l) * inv;
        uint2 v = *(const uint2*)&h2[(size_t)s * HID + lane * 4];
        float2 f0 = __half22float2(*(__half2*)&v.x);
        float2 f1 = __half22float2(*(__half2*)&v.y);
        a0 += al * f0.x; a1 += al * f0.y;
        a2 += al * f1.x; a3 += al * f1.y;
    }
    float4 b = *(const float4*)&b2[lane * 4];
    __half2 p0 = __floats2half2_rn(fmaxf(a0 + b.x, 0.f), fmaxf(a1 + b.y, 0.f));
    __half2 p1 = __floats2half2_rn(fmaxf(a2 + b.z, 0.f), fmaxf(a3 + b.w, 0.f));
    uint2 o;
    o.x = *(unsigned*)&p0; o.y = *(unsigned*)&p1;
    *(uint2*)&g_out2h[((size_t)t * NN + n) * HID + lane * 4] = o;
}

// ---------------- deterministic mean pool (batched) ----------------
__global__ void __launch_bounds__(128) k_pool_a() {
    int c = threadIdx.x, b = blockIdx.x, t = blockIdx.y;
    int n0 = b * PCH, n1 = min(n0 + PCH, NN);
    float s = 0.f;
    for (int n = n0; n < n1; n++)
        s += __half2float(g_out2h[((size_t)t * NN + n) * HID + c]);
    g_partial[((size_t)t * PBLK + b) * HID + c] = s;
}

__global__ void __launch_bounds__(128) k_pool_b() {
    int c = threadIdx.x, t = blockIdx.x;
    float s = 0.f;
    for (int b = 0; b < PBLK; b++) s += g_partial[((size_t)t * PBLK + b) * HID + c];
    g_emb[t * HID + c] = s * (1.0f / NN);
}

// ---------------- GRU + output head ----------------
__global__ void __launch_bounds__(128) k_gru(
    const float* __restrict__ wih, const float* __restrict__ whh,
    const float* __restrict__ bih, const float* __restrict__ bhh,
    const float* __restrict__ wout, const float* __restrict__ bout,
    float* __restrict__ out) {
    int tid = threadIdx.x;
    __shared__ float h[HID], xt[HID];
    __shared__ float red[4];
    h[tid] = 0.f;
    __syncthreads();
    for (int t = 0; t < TT; t++) {
        xt[tid] = g_emb[t * HID + tid];
        __syncthreads();
        float gi[3], gh[3];
#pragma unroll
        for (int q = 0; q < 3; q++) {
            int r = q * HID + tid;
            float s1 = bih[r], s2 = bhh[r];
            const float* wi = &wih[(size_t)r * HID];
            const float* wh = &whh[(size_t)r * HID];
            for (int c = 0; c < HID; c++) {
                s1 += xt[c] * wi[c];
                s2 += h[c] * wh[c];
            }
            gi[q] = s1;
            gh[q] = s2;
        }
        float r  = 1.f / (1.f + __expf(-(gi[0] + gh[0])));
        float z  = 1.f / (1.f + __expf(-(gi[1] + gh[1])));
        float nn = tanhf(gi[2] + r * gh[2]);
        float hn = (1.f - z) * nn + z * h[tid];
        __syncthreads();
        h[tid] = hn;
        __syncthreads();
        float v = hn * wout[tid];
        int lane = tid & 31, w = tid >> 5;
        for (int o = 16; o; o >>= 1) v += __shfl_down_sync(FULL, v, o);
        if (lane == 0) red[w] = v;
        __syncthreads();
        if (tid == 0) out[t] = red[0] + red[1] + red[2] + red[3] + bout[0];
        __syncthreads();
    }
}

// ---------------- launch ----------------
extern "C" void kernel_launch(void* const* d_in, const int* in_sizes, int n_in,
                              void* d_out, int out_size) {
    const float* x    = (const float*)d_in[0];
    const void*  ei   = d_in[1];
    const float* W1   = (const float*)d_in[2];
    const float* as1  = (const float*)d_in[3];
    const float* ad1  = (const float*)d_in[4];
    const float* b1   = (const float*)d_in[5];
    const float* W2   = (const float*)d_in[6];
    const float* as2  = (const float*)d_in[7];
    const float* ad2  = (const float*)d_in[8];
    const float* b2   = (const float*)d_in[9];
    const float* wih  = (const float*)d_in[10];
    const float* whh  = (const float*)d_in[11];
    const float* bih  = (const float*)d_in[12];
    const float* bhh  = (const float*)d_in[13];
    const float* wout = (const float*)d_in[14];
    const float* bout = (const float*)d_in[15];
    float* out = (float*)d_out;

    k_zc<<<(NN + 255) / 256, 256>>>();
    k_count<<<(EE + 255) / 256, 256>>>(ei);
    k_prep<<<(D1 * HID + 255) / 256, 256>>>(W2, W1, as1, ad1);
    k_logits1<<<(TT * NN + 255) / 256, 256>>>(x);
    k_scan<<<1, 1024>>>();
    k_fill<<<(EE + 255) / 256, 256>>>(ei);
    k_agg1x<<<dim3((NN + 7) / 8, TT), 256>>>(x);
    k_expand<<<MM / 32, 256>>>(W1, b1);
    k_gemm<<<MM / 128, 256>>>();
    k_al2<<<dim3((NN + 7) / 8, TT), 256>>>(as2, ad2);
    k_agg2<<<dim3((NN + 7) / 8, TT), 256>>>(b2);
    k_pool_a<<<dim3(PBLK, TT), 128>>>();
    k_pool_b<<<TT, 128>>>();
    k_gru<<<1, 128>>>(wih, whh, bih, bhh, wout, bout, out);
}